// round 14
// baseline (speedup 1.0000x reference)
#include <cuda_runtime.h>

#define NTAGS 64
#define SOS_IDX 1
#define EOS_IDX 2
#define REF_TAG 3
#define MAXB 1024
#define NWORKER 148

__device__ int g_len[MAXB];
__device__ int g_order[MAXB];
__device__ int g_ctr;

static __device__ __forceinline__ unsigned long long pk2(float x, float y) {
    unsigned long long r;
    asm("mov.b64 %0, {%1, %2};" : "=l"(r) : "f"(x), "f"(y));
    return r;
}
static __device__ __forceinline__ void upk2(unsigned long long a, float &x, float &y) {
    asm("mov.b64 {%0, %1}, %2;" : "=f"(x), "=f"(y) : "l"(a));
}
static __device__ __forceinline__ unsigned long long fma2(unsigned long long a,
                                                          unsigned long long b,
                                                          unsigned long long c) {
    unsigned long long d;
    asm("fma.rn.f32x2 %0, %1, %2, %3;" : "=l"(d) : "l"(a), "l"(b), "l"(c));
    return d;
}
static __device__ __forceinline__ unsigned long long add2(unsigned long long a,
                                                          unsigned long long b) {
    unsigned long long d;
    asm("add.rn.f32x2 %0, %1, %2;" : "=l"(d) : "l"(a), "l"(b));
    return d;
}

// ---- kernel 1: lengths (mask is a prefix of ones) ----
__global__ void __launch_bounds__(NTAGS) len_kernel(
    const float* __restrict__ mask, int T)
{
    const int b = blockIdx.x;
    const int i = threadIdx.x;
    const float4* m4 = reinterpret_cast<const float4*>(mask + (size_t)b * T);
    float msum = 0.0f;
    const int n4 = T >> 2;
    for (int k = i; k < n4; k += NTAGS) {
        float4 v = m4[k];
        msum += (v.x + v.y) + (v.z + v.w);
    }
    #pragma unroll
    for (int o = 16; o > 0; o >>= 1) msum += __shfl_xor_sync(0xffffffffu, msum, o);
    __shared__ float sh[2];
    if ((i & 31) == 0) sh[i >> 5] = msum;
    __syncthreads();
    if (i == 0) g_len[b] = (int)(sh[0] + sh[1] + 0.5f);
}

// ---- kernel 2: sort ids by length descending (bitonic, one block), reset ctr ----
__global__ void sort_kernel(int B, int n /* pow2 >= B */)
{
    extern __shared__ int smem_sort[];
    int* key = smem_sort;          // -len (ascending sort -> longest first)
    int* val = smem_sort + n;
    const int tid = threadIdx.x;
    if (tid < n) {
        key[tid] = (tid < B) ? -g_len[tid] : 0x7fffffff;
        val[tid] = tid;
    }
    __syncthreads();
    for (int k = 2; k <= n; k <<= 1) {
        for (int j = k >> 1; j > 0; j >>= 1) {
            int ixj = tid ^ j;
            if (ixj > tid && tid < n) {
                bool up = ((tid & k) == 0);
                int ka = key[tid], kb = key[ixj];
                if ((ka > kb) == up) {
                    key[tid] = kb; key[ixj] = ka;
                    int va = val[tid]; val[tid] = val[ixj]; val[ixj] = va;
                }
            }
            __syncthreads();
        }
    }
    if (tid < B) g_order[tid] = val[tid];
    if (tid == 0) g_ctr = 0;
}

// full R12-style step body for one chain; relies on compile-time-constant t&3
#define CHAIN_STEP(upbuf, unbuf, hb, rawh, ehcur, myu, Esum)                        \
    {                                                                               \
        const float* up = upbuf;                                                    \
        float* un = unbuf;                                                          \
        const float4* pv = reinterpret_cast<const float4*>(up);                     \
        const unsigned int ub = __float_as_uint(up[REF_TAG]);                       \
        unsigned long long acc[8];                                                  \
        float4 pa[8];                                                               \
        _Pragma("unroll")                                                           \
        for (int k = 0; k < 8; k++) pa[k] = pv[k];                                  \
        int tp = t + 4;                                                             \
        tp = (tp < T) ? tp : (T - 1);                                               \
        float fresh = hb[(size_t)tp * NTAGS];                                       \
        float ehnext = __expf(rawh[(t + 1) & 3]);                                   \
        rawh[t & 3] = fresh;                                                        \
        const float eh = ehcur;                                                     \
        ehcur = ehnext;                                                             \
        int e = (int)((ub >> 23) & 0xffu) - 127;                                    \
        e = (ub == 0u) ? 0 : e;                                                     \
        const float scale = __uint_as_float((unsigned)(127 - e) << 23);             \
        Esum += e;                                                                  \
        const float es = eh * scale;                                                \
        _Pragma("unroll")                                                           \
        for (int k = 0; k < 8; k++) {                                               \
            const int a0 = (k & 3) * 2;                                             \
            unsigned long long lo = fma2(E2[2 * k], pk2(pa[k].x, pa[k].y),          \
                                         (k < 4) ? 0ull : acc[a0]);                 \
            unsigned long long hi = fma2(E2[2 * k + 1], pk2(pa[k].z, pa[k].w),      \
                                         (k < 4) ? 0ull : acc[a0 + 1]);             \
            acc[a0] = lo; acc[a0 + 1] = hi;                                         \
        }                                                                           \
        _Pragma("unroll")                                                           \
        for (int k = 0; k < 8; k++) pa[k] = pv[k + 8];                              \
        _Pragma("unroll")                                                           \
        for (int k = 0; k < 8; k++) {                                               \
            const int a0 = (k & 3) * 2;                                             \
            acc[a0]     = fma2(E2[2 * (k + 8)],     pk2(pa[k].x, pa[k].y), acc[a0]);\
            acc[a0 + 1] = fma2(E2[2 * (k + 8) + 1], pk2(pa[k].z, pa[k].w), acc[a0 + 1]);\
        }                                                                           \
        unsigned long long sA = add2(add2(add2(acc[0], acc[2]), add2(acc[4], acc[6])),\
                                     add2(add2(acc[1], acc[3]), add2(acc[5], acc[7])));\
        float vx, vy;                                                               \
        upk2(sA, vx, vy);                                                           \
        const float u = es * (vx + vy);                                             \
        un[i] = u;                                                                  \
        myu = u;                                                                    \
    }

// ---- kernel 3: persistent workers, one PAIR of sorted-adjacent chains each ----
__global__ void __launch_bounds__(NTAGS) crf_main_kernel(
    const float* __restrict__ h, const float* __restrict__ mask,
    const float* __restrict__ trans, float* __restrict__ out, int T, int B)
{
    const int i = threadIdx.x;          // one thread per tag
    const int warp = i >> 5;
    const int lane = i & 31;

    __shared__ __align__(16) float sh_uA[2][NTAGS];
    __shared__ __align__(16) float sh_uB[2][NTAGS];
    __shared__ float sh_red[4];
    __shared__ int sh_idx;

    // E[i][j] = exp(trans[i][j]) packed as f32x2 (shared by both chains).
    // exp(-10000) underflows to exactly 0 -> masked transitions vanish.
    unsigned long long E2[NTAGS / 2];
    {
        const float4* tr = reinterpret_cast<const float4*>(trans + i * NTAGS);
        #pragma unroll
        for (int k = 0; k < NTAGS / 4; k++) {
            float4 t4 = tr[k];
            E2[2 * k]     = pk2(__expf(t4.x), __expf(t4.y));
            E2[2 * k + 1] = pk2(__expf(t4.z), __expf(t4.w));
        }
    }
    const float eeos = __expf(trans[EOS_IDX * NTAGS + i]);
    const int npair = (B + 1) >> 1;

    for (;;) {
        if (i == 0) sh_idx = atomicAdd(&g_ctr, 1);
        __syncthreads();
        const int idx = sh_idx;
        if (idx >= npair) break;        // uniform exit
        const int bA = g_order[2 * idx];
        const bool hasB = (2 * idx + 1 < B);
        const int bB = hasB ? g_order[2 * idx + 1] : bA;
        const int lenA = g_len[bA];
        const int lenB = hasB ? g_len[bB] : 0;
        const int lenP = (lenA > lenB) ? lenA : lenB;

        const float* hbA = h + (size_t)bA * T * NTAGS + i;
        const float* hbB = h + (size_t)bB * T * NTAGS + i;

        float rawhA[4], rawhB[4];
        #pragma unroll
        for (int k = 0; k < 4; k++) {
            int tp = (k < T) ? k : (T - 1);
            rawhA[k] = hbA[(size_t)tp * NTAGS];
            rawhB[k] = hbB[(size_t)tp * NTAGS];
        }

        const float u0 = (i == SOS_IDX) ? 1.0f : 0.0f;
        sh_uA[0][i] = u0;
        sh_uB[0][i] = u0;
        float myuA = u0, myuB = u0;
        int EsumA = 0, EsumB = 0;
        float ehcurA = __expf(rawhA[0]);
        float ehcurB = __expf(rawhB[0]);
        __syncthreads();

        #pragma unroll 4
        for (int t = 0; t < lenP; t++) {
            if (t < lenA)               // CTA-uniform guard
                CHAIN_STEP(sh_uA[t & 1], sh_uA[(t + 1) & 1], hbA, rawhA, ehcurA, myuA, EsumA)
            if (t < lenB)               // CTA-uniform guard
                CHAIN_STEP(sh_uB[t & 1], sh_uB[(t + 1) & 1], hbB, rawhB, ehcurB, myuB, EsumB)
            __syncthreads();            // one barrier for both chains
        }

        // finals: out[b] = Esum*ln2 + log(sum_i U_i * exp(trans[EOS,i]))
        float tA = myuA * eeos;
        float tB = myuB * eeos;
        #pragma unroll
        for (int o = 16; o > 0; o >>= 1) {
            tA += __shfl_xor_sync(0xffffffffu, tA, o);
            tB += __shfl_xor_sync(0xffffffffu, tB, o);
        }
        __syncthreads();
        if (lane == 0) { sh_red[warp] = tA; sh_red[2 + warp] = tB; }
        __syncthreads();
        if (i == 0) {
            out[bA] = (float)EsumA * 0.6931471805599453f + __logf(sh_red[0] + sh_red[1]);
            if (hasB)
                out[bB] = (float)EsumB * 0.6931471805599453f + __logf(sh_red[2] + sh_red[3]);
        }
        __syncthreads();                // protect smem before next pair
    }
}

extern "C" void kernel_launch(void* const* d_in, const int* in_sizes, int n_in,
                              void* d_out, int out_size) {
    const float* h     = (const float*)d_in[0];   // [B, T, 64]
    const float* mask  = (const float*)d_in[1];   // [B, T]
    const float* trans = (const float*)d_in[2];   // [64, 64]
    float* out = (float*)d_out;                   // [B]
    const int B = out_size;
    const int T = in_sizes[1] / B;
    int n = 1;
    while (n < B) n <<= 1;                        // pow2 for bitonic
    len_kernel<<<B, NTAGS>>>(mask, T);
    sort_kernel<<<1, n, 2 * n * sizeof(int)>>>(B, n);
    crf_main_kernel<<<NWORKER, NTAGS>>>(h, mask, trans, out, T, B);
}

// round 15
// speedup vs baseline: 2.0771x; 2.0771x over previous
#include <cuda_runtime.h>

#define NTAGS 64
#define SOS_IDX 1
#define EOS_IDX 2
#define REF_TAG 3
#define MAXB 1024
#define NWORKER 148

__device__ int g_len[MAXB];
__device__ int g_order[MAXB];
__device__ int g_ctr;

static __device__ __forceinline__ unsigned long long pk2(float x, float y) {
    unsigned long long r;
    asm("mov.b64 %0, {%1, %2};" : "=l"(r) : "f"(x), "f"(y));
    return r;
}
static __device__ __forceinline__ void upk2(unsigned long long a, float &x, float &y) {
    asm("mov.b64 {%0, %1}, %2;" : "=f"(x), "=f"(y) : "l"(a));
}
static __device__ __forceinline__ unsigned long long fma2(unsigned long long a,
                                                          unsigned long long b,
                                                          unsigned long long c) {
    unsigned long long d;
    asm("fma.rn.f32x2 %0, %1, %2, %3;" : "=l"(d) : "l"(a), "l"(b), "l"(c));
    return d;
}
static __device__ __forceinline__ unsigned long long add2(unsigned long long a,
                                                          unsigned long long b) {
    unsigned long long d;
    asm("add.rn.f32x2 %0, %1, %2;" : "=l"(d) : "l"(a), "l"(b));
    return d;
}

// ---- kernel 1: lengths (mask is a prefix of ones) ----
__global__ void __launch_bounds__(NTAGS) len_kernel(
    const float* __restrict__ mask, int T)
{
    const int b = blockIdx.x;
    const int i = threadIdx.x;
    const float4* m4 = reinterpret_cast<const float4*>(mask + (size_t)b * T);
    float msum = 0.0f;
    const int n4 = T >> 2;
    for (int k = i; k < n4; k += NTAGS) {
        float4 v = m4[k];
        msum += (v.x + v.y) + (v.z + v.w);
    }
    #pragma unroll
    for (int o = 16; o > 0; o >>= 1) msum += __shfl_xor_sync(0xffffffffu, msum, o);
    __shared__ float sh[2];
    if ((i & 31) == 0) sh[i >> 5] = msum;
    __syncthreads();
    if (i == 0) g_len[b] = (int)(sh[0] + sh[1] + 0.5f);
}

// ---- kernel 2: sort ids by length descending (bitonic, one block), reset ctr ----
__global__ void sort_kernel(int B, int n /* pow2 >= B */)
{
    extern __shared__ int smem_sort[];
    int* key = smem_sort;          // -len (ascending sort -> longest first)
    int* val = smem_sort + n;
    const int tid = threadIdx.x;
    if (tid < n) {
        key[tid] = (tid < B) ? -g_len[tid] : 0x7fffffff;
        val[tid] = tid;
    }
    __syncthreads();
    for (int k = 2; k <= n; k <<= 1) {
        for (int j = k >> 1; j > 0; j >>= 1) {
            int ixj = tid ^ j;
            if (ixj > tid && tid < n) {
                bool up = ((tid & k) == 0);
                int ka = key[tid], kb = key[ixj];
                if ((ka > kb) == up) {
                    key[tid] = kb; key[ixj] = ka;
                    int va = val[tid]; val[tid] = val[ixj]; val[ixj] = va;
                }
            }
            __syncthreads();
        }
    }
    if (tid < B) g_order[tid] = val[tid];
    if (tid == 0) g_ctr = 0;
}

// dot + update body shared by main and tail loops (eh already available)
#define DOT_BODY(upbuf, unbuf, EH)                                                   \
    {                                                                                \
        const float* up = upbuf;                                                     \
        float* un = unbuf;                                                           \
        const float4* pv = reinterpret_cast<const float4*>(up);                      \
        const unsigned int ub = __float_as_uint(up[REF_TAG]);                        \
        unsigned long long acc[8];                                                   \
        float4 pa[8];                                                                \
        _Pragma("unroll")                                                            \
        for (int k = 0; k < 8; k++) pa[k] = pv[k];                                   \
        const int e = (int)((ub >> 23) & 0xffu) - 127;   /* U_REF > 0 for t>=1 */    \
        const float scale = __uint_as_float((unsigned)(127 - e) << 23);              \
        Esum += e;                                                                   \
        const float es = (EH) * scale;                                               \
        _Pragma("unroll")                                                            \
        for (int k = 0; k < 8; k++) {                                                \
            const int a0 = (k & 3) * 2;                                              \
            unsigned long long lo = fma2(E2[2 * k], pk2(pa[k].x, pa[k].y),           \
                                         (k < 4) ? 0ull : acc[a0]);                  \
            unsigned long long hi = fma2(E2[2 * k + 1], pk2(pa[k].z, pa[k].w),       \
                                         (k < 4) ? 0ull : acc[a0 + 1]);              \
            acc[a0] = lo; acc[a0 + 1] = hi;                                          \
        }                                                                            \
        _Pragma("unroll")                                                            \
        for (int k = 0; k < 8; k++) pa[k] = pv[k + 8];                               \
        _Pragma("unroll")                                                            \
        for (int k = 0; k < 8; k++) {                                                \
            const int a0 = (k & 3) * 2;                                              \
            acc[a0]     = fma2(E2[2 * (k + 8)],     pk2(pa[k].x, pa[k].y), acc[a0]); \
            acc[a0 + 1] = fma2(E2[2 * (k + 8) + 1], pk2(pa[k].z, pa[k].w), acc[a0 + 1]);\
        }                                                                            \
        unsigned long long sA = add2(add2(add2(acc[0], acc[2]), add2(acc[4], acc[6])),\
                                     add2(add2(acc[1], acc[3]), add2(acc[5], acc[7])));\
        float vx, vy;                                                                \
        upk2(sA, vx, vy);                                                            \
        const float u = es * (vx + vy);                                              \
        un[i] = u;                                                                   \
        myu = u;                                                                     \
    }

// ---- kernel 3: persistent workers, longest chains first ----
__global__ void __launch_bounds__(NTAGS) crf_main_kernel(
    const float* __restrict__ h, const float* __restrict__ mask,
    const float* __restrict__ trans, float* __restrict__ out, int T, int B)
{
    const int i = threadIdx.x;          // one thread per tag
    const int warp = i >> 5;
    const int lane = i & 31;

    __shared__ __align__(16) float sh_u[2][NTAGS];
    __shared__ float sh_red[2];
    __shared__ int sh_idx;

    // E[i][j] = exp(trans[i][j]) packed as f32x2 (constant over all chains).
    // exp(-10000) underflows to exactly 0 -> masked transitions vanish.
    unsigned long long E2[NTAGS / 2];
    {
        const float4* tr = reinterpret_cast<const float4*>(trans + i * NTAGS);
        #pragma unroll
        for (int k = 0; k < NTAGS / 4; k++) {
            float4 t4 = tr[k];
            E2[2 * k]     = pk2(__expf(t4.x), __expf(t4.y));
            E2[2 * k + 1] = pk2(__expf(t4.z), __expf(t4.w));
        }
    }
    const float eeos = __expf(trans[EOS_IDX * NTAGS + i]);

    for (;;) {
        if (i == 0) sh_idx = atomicAdd(&g_ctr, 1);
        __syncthreads();
        const int idx = sh_idx;
        if (idx >= B) break;            // uniform exit
        const int b = g_order[idx];
        const int len = g_len[b];
        const float* hb = h + (size_t)b * T * NTAGS + i;

        // raw prefetch buffers (depth 4); T >= 5 always here (T = 1024)
        float rawh[4];
        #pragma unroll
        for (int k = 0; k < 4; k++) rawh[k] = hb[(size_t)k * NTAGS];

        // ---- peeled t = 0: U(0)_i = exp(h0_i) * E[i][SOS], no exchange ----
        float ehcur = __expf(rawh[0]);
        float e0x, e0y;
        upk2(E2[0], e0x, e0y);          // e0y = exp(trans[i][1]) = E[i][SOS]
        float myu = ehcur * e0y;
        sh_u[1][i] = myu;               // buffer (0+1)&1 = 1
        int Esum = 0;
        ehcur = __expf(rawh[1]);        // exp for t = 1, computed early
        rawh[0] = hb[(size_t)4 * NTAGS];
        __syncthreads();

        // ---- main loop: t = 1 .. lim-1, clamp-free pointer prefetch ----
        const int lim = (len < T - 4) ? len : (T - 4);
        const float* hp = hb + (size_t)5 * NTAGS;   // h[t+4] for t = 1
        const int nmain = lim - 1;
        #pragma unroll 4
        for (int s = 0; s < nmain; s++) {
            const int t = s + 1;
            const float fresh = *hp;
            hp += NTAGS;
            const float ehnext = __expf(rawh[(t + 1) & 3]);  // loaded at t-3
            rawh[t & 3] = fresh;
            const float eh = ehcur;
            ehcur = ehnext;
            DOT_BODY(sh_u[t & 1], sh_u[(t + 1) & 1], eh)
            __syncthreads();            // single barrier per step
        }

        // ---- tail: t = lim .. len-1 (at most 4 steps; only near-T chains) ----
        // direct h loads; rawh untouched so it stays register-resident.
        #pragma unroll 1
        for (int t = lim; t < len; t++) {
            const float eh = __expf(hb[(size_t)t * NTAGS]);
            DOT_BODY(sh_u[t & 1], sh_u[(t + 1) & 1], eh)
            __syncthreads();
        }

        // out[b] = Esum*ln2 + log( sum_i U_i * exp(trans[EOS,i]) )
        float term = myu * eeos;
        #pragma unroll
        for (int o = 16; o > 0; o >>= 1) term += __shfl_xor_sync(0xffffffffu, term, o);
        __syncthreads();
        if (lane == 0) sh_red[warp] = term;
        __syncthreads();
        if (i == 0) {
            out[b] = (float)Esum * 0.6931471805599453f + __logf(sh_red[0] + sh_red[1]);
        }
        __syncthreads();                // protect sh_u/sh_red before next chain
    }
}

extern "C" void kernel_launch(void* const* d_in, const int* in_sizes, int n_in,
                              void* d_out, int out_size) {
    const float* h     = (const float*)d_in[0];   // [B, T, 64]
    const float* mask  = (const float*)d_in[1];   // [B, T]
    const float* trans = (const float*)d_in[2];   // [64, 64]
    float* out = (float*)d_out;                   // [B]
    const int B = out_size;
    const int T = in_sizes[1] / B;
    int n = 1;
    while (n < B) n <<= 1;                        // pow2 for bitonic
    len_kernel<<<B, NTAGS>>>(mask, T);
    sort_kernel<<<1, n, 2 * n * sizeof(int)>>>(B, n);
    crf_main_kernel<<<NWORKER, NTAGS>>>(h, mask, trans, out, T, B);
}

// round 16
// speedup vs baseline: 3.1739x; 1.5281x over previous
#include <cuda_runtime.h>

#define NTAGS 64
#define SOS_IDX 1
#define EOS_IDX 2
#define REF_TAG 3
#define MAXB 1024
#define NWORKER 148

__device__ int g_len[MAXB];
__device__ int g_order[MAXB];
__device__ int g_ctr;

static __device__ __forceinline__ unsigned long long pk2(float x, float y) {
    unsigned long long r;
    asm("mov.b64 %0, {%1, %2};" : "=l"(r) : "f"(x), "f"(y));
    return r;
}
static __device__ __forceinline__ void upk2(unsigned long long a, float &x, float &y) {
    asm("mov.b64 {%0, %1}, %2;" : "=f"(x), "=f"(y) : "l"(a));
}
static __device__ __forceinline__ unsigned long long fma2(unsigned long long a,
                                                          unsigned long long b,
                                                          unsigned long long c) {
    unsigned long long d;
    asm("fma.rn.f32x2 %0, %1, %2, %3;" : "=l"(d) : "l"(a), "l"(b), "l"(c));
    return d;
}
static __device__ __forceinline__ unsigned long long add2(unsigned long long a,
                                                          unsigned long long b) {
    unsigned long long d;
    asm("add.rn.f32x2 %0, %1, %2;" : "=l"(d) : "l"(a), "l"(b));
    return d;
}

// ---- kernel 1: lengths (mask is a prefix of ones), 256 threads/row ----
__global__ void __launch_bounds__(256) len_kernel(
    const float* __restrict__ mask, int T)
{
    const int b = blockIdx.x;
    const int tid = threadIdx.x;
    const int lane = tid & 31;
    const int warp = tid >> 5;
    const float4* m4 = reinterpret_cast<const float4*>(mask + (size_t)b * T);
    const int n4 = T >> 2;
    float msum = 0.0f;
    for (int k = tid; k < n4; k += 256) {
        float4 v = m4[k];
        msum += (v.x + v.y) + (v.z + v.w);
    }
    #pragma unroll
    for (int o = 16; o > 0; o >>= 1) msum += __shfl_xor_sync(0xffffffffu, msum, o);
    __shared__ float sh[8];
    if (lane == 0) sh[warp] = msum;
    __syncthreads();
    if (tid == 0) {
        float s = 0.0f;
        #pragma unroll
        for (int k = 0; k < 8; k++) s += sh[k];
        g_len[b] = (int)(s + 0.5f);
    }
}

// ---- kernel 2: sort ids by length descending (bitonic, one block), reset ctr ----
__global__ void sort_kernel(int B, int n /* pow2 >= B */)
{
    extern __shared__ int smem_sort[];
    int* key = smem_sort;          // -len (ascending sort -> longest first)
    int* val = smem_sort + n;
    const int tid = threadIdx.x;
    if (tid < n) {
        key[tid] = (tid < B) ? -g_len[tid] : 0x7fffffff;
        val[tid] = tid;
    }
    __syncthreads();
    for (int k = 2; k <= n; k <<= 1) {
        for (int j = k >> 1; j > 0; j >>= 1) {
            int ixj = tid ^ j;
            if (ixj > tid && tid < n) {
                bool up = ((tid & k) == 0);
                int ka = key[tid], kb = key[ixj];
                if ((ka > kb) == up) {
                    key[tid] = kb; key[ixj] = ka;
                    int va = val[tid]; val[tid] = val[ixj]; val[ixj] = va;
                }
            }
            __syncthreads();
        }
    }
    if (tid < B) g_order[tid] = val[tid];
    if (tid == 0) g_ctr = 0;
}

// ---- kernel 3: persistent workers, longest chains first (R12, verbatim) ----
__global__ void __launch_bounds__(NTAGS) crf_main_kernel(
    const float* __restrict__ h, const float* __restrict__ mask,
    const float* __restrict__ trans, float* __restrict__ out, int T, int B)
{
    const int i = threadIdx.x;          // one thread per tag
    const int warp = i >> 5;
    const int lane = i & 31;

    __shared__ __align__(16) float sh_u[2][NTAGS];
    __shared__ float sh_red[2];
    __shared__ int sh_idx;

    // E[i][j] = exp(trans[i][j]) packed as f32x2 (constant over all chains).
    // exp(-10000) underflows to exactly 0 -> masked transitions vanish.
    unsigned long long E2[NTAGS / 2];
    {
        const float4* tr = reinterpret_cast<const float4*>(trans + i * NTAGS);
        #pragma unroll
        for (int k = 0; k < NTAGS / 4; k++) {
            float4 t4 = tr[k];
            E2[2 * k]     = pk2(__expf(t4.x), __expf(t4.y));
            E2[2 * k + 1] = pk2(__expf(t4.z), __expf(t4.w));
        }
    }
    const float eeos = __expf(trans[EOS_IDX * NTAGS + i]);

    for (;;) {
        if (i == 0) sh_idx = atomicAdd(&g_ctr, 1);
        __syncthreads();
        const int idx = sh_idx;
        if (idx >= B) break;            // uniform exit
        const int b = g_order[idx];
        const int len = g_len[b];
        const float* hb = h + (size_t)b * T * NTAGS + i;

        // raw prefetch buffers (depth 4)
        float rawh[4];
        #pragma unroll
        for (int k = 0; k < 4; k++) {
            int tp = (k < T) ? k : (T - 1);
            rawh[k] = hb[(size_t)tp * NTAGS];
        }

        // U(-1): 1 at SOS, 0 elsewhere.
        sh_u[0][i] = (i == SOS_IDX) ? 1.0f : 0.0f;
        float myu = (i == SOS_IDX) ? 1.0f : 0.0f;
        int Esum = 0;
        float ehcur = __expf(rawh[0]);  // exp computed one full step ahead
        __syncthreads();

        #pragma unroll 4
        for (int t = 0; t < len; t++) {
            const float* up = sh_u[t & 1];
            float* un = sh_u[(t + 1) & 1];
            const float4* pv = reinterpret_cast<const float4*>(up);

            // issue all shared loads first: renorm scalar + 16 LDS.128
            const unsigned int ub = __float_as_uint(up[REF_TAG]);
            float4 pa[16];
            #pragma unroll
            for (int k = 0; k < 16; k++) pa[k] = pv[k];

            // independent work overlapping LDS latency: h(t+4), exp(t+1)
            int tp = t + 4;
            tp = (tp < T) ? tp : (T - 1);
            float fresh = hb[(size_t)tp * NTAGS];
            float ehnext = __expf(rawh[(t + 1) & 3]);   // loaded at t-3
            rawh[t & 3] = fresh;
            const float eh = ehcur;
            ehcur = ehnext;

            // exact power-of-two renormalizer (ALU-only, off the dot path)
            int e = (int)((ub >> 23) & 0xffu) - 127;
            e = (ub == 0u) ? 0 : e;         // t==0: uref is exactly 0
            const float scale = __uint_as_float((unsigned)(127 - e) << 23);
            Esum += e;
            const float es = eh * scale;

            // w_i = dot(E_row_i, U_prev): 32 fma2, 8 independent accumulators
            unsigned long long acc[8];
            #pragma unroll
            for (int k = 0; k < 16; k++) {
                const int a0 = (k & 3) * 2;
                unsigned long long lo = fma2(E2[2 * k],     pk2(pa[k].x, pa[k].y),
                                             (k < 4) ? 0ull : acc[a0]);
                unsigned long long hi = fma2(E2[2 * k + 1], pk2(pa[k].z, pa[k].w),
                                             (k < 4) ? 0ull : acc[a0 + 1]);
                acc[a0] = lo; acc[a0 + 1] = hi;
            }
            unsigned long long sA = add2(add2(add2(acc[0], acc[2]), add2(acc[4], acc[6])),
                                         add2(add2(acc[1], acc[3]), add2(acc[5], acc[7])));
            float vx, vy;
            upk2(sA, vx, vy);
            const float w = vx + vy;

            const float u = es * w;         // U_i(t)
            un[i] = u;
            myu = u;
            __syncthreads();                // single barrier per step
        }

        // out[b] = Esum*ln2 + log( sum_i U_i * exp(trans[EOS,i]) )
        float term = myu * eeos;
        #pragma unroll
        for (int o = 16; o > 0; o >>= 1) term += __shfl_xor_sync(0xffffffffu, term, o);
        __syncthreads();
        if (lane == 0) sh_red[warp] = term;
        __syncthreads();
        if (i == 0) {
            out[b] = (float)Esum * 0.6931471805599453f + __logf(sh_red[0] + sh_red[1]);
        }
        __syncthreads();                    // protect sh_u/sh_red before next chain
    }
}

extern "C" void kernel_launch(void* const* d_in, const int* in_sizes, int n_in,
                              void* d_out, int out_size) {
    const float* h     = (const float*)d_in[0];   // [B, T, 64]
    const float* mask  = (const float*)d_in[1];   // [B, T]
    const float* trans = (const float*)d_in[2];   // [64, 64]
    float* out = (float*)d_out;                   // [B]
    const int B = out_size;
    const int T = in_sizes[1] / B;
    int n = 1;
    while (n < B) n <<= 1;                        // pow2 for bitonic
    len_kernel<<<B, 256>>>(mask, T);
    sort_kernel<<<1, n, 2 * n * sizeof(int)>>>(B, n);
    crf_main_kernel<<<NWORKER, NTAGS>>>(h, mask, trans, out, T, B);
}